// round 15
// baseline (speedup 1.0000x reference)
#include <cuda_runtime.h>

#define BB 64
#define SS 1024
#define DD 1024
#define VV 1024

typedef unsigned long long ull;

// ---------------- scratch (no allocation allowed) ----------------
// zeroed-every-call region (zeroed by k_init):
//   [0]      w2    (64K floats)
//   [64K]    wsum  (64K)   <- assembled by atomics across stepA/stepB
//   [128K]   accv  (64K)
//   [192K]   gs    (64K)
//   [256K]   hpre  (128K) -> [64][2048] (ho_pre | hf_pre)
__device__ float g_zbuf[BB * SS * 4 + BB * 2048];

#define OFF_W2   0
#define OFF_WSUM (BB * SS)
#define OFF_ACCV (BB * SS * 2)
#define OFF_GS   (BB * SS * 3)
#define OFF_HPRE (BB * SS * 4)
#define NZ       (BB * SS * 4 + BB * 2048)   // 393216 floats to zero

#define ROWS 128           // s-rows per CTA per pass (grid = 8 x 64 = 512 CTAs)

// ---- PDL primitives (no-ops when kernel not launched with the attribute) ----
__device__ __forceinline__ void pdl_trigger() {
    asm volatile("griddepcontrol.launch_dependents;");
}
__device__ __forceinline__ void pdl_wait() {
    asm volatile("griddepcontrol.wait;" ::: "memory");
}

// ---- f32x2 packed helpers (FFMA2 exists on sm_103a only via PTX) ----
__device__ __forceinline__ ull pack_bcast(float x) {
    ull r;
    asm("mov.b64 %0, {%1, %1};" : "=l"(r) : "r"(__float_as_uint(x)));
    return r;
}
__device__ __forceinline__ ull fma2(ull a, ull b, ull c) {
    ull r;
    asm("fma.rn.f32x2 %0, %1, %2, %3;" : "=l"(r) : "l"(a), "l"(b), "l"(c));
    return r;
}
__device__ __forceinline__ float2 unpack2(ull v) {
    unsigned lo, hi;
    asm("mov.b64 {%0, %1}, %2;" : "=r"(lo), "=r"(hi) : "l"(v));
    return make_float2(__uint_as_float(lo), __uint_as_float(hi));
}

// ---- matvec accumulate: rows 8..ROWS with first 8 rows prefetched in m0 ----
__device__ __forceinline__ void matvec_acc(
    const float* __restrict__ Mb, const float4* m0, const float* xs, int t0,
    float& a0, float& a1, float& a2, float& a3)
{
#pragma unroll
    for (int j = 0; j < 8; ++j) {
        float x = xs[j];
        a0 += x * m0[j].x; a1 += x * m0[j].y;
        a2 += x * m0[j].z; a3 += x * m0[j].w;
    }
#pragma unroll 1
    for (int s = 8; s < ROWS; s += 8) {
        float4 m[8];
#pragma unroll
        for (int j = 0; j < 8; ++j)
            m[j] = __ldcs(reinterpret_cast<const float4*>(Mb + (size_t)(s + j) * SS + t0));
#pragma unroll
        for (int j = 0; j < 8; ++j) {
            float x = xs[s + j];
            a0 += x * m[j].x; a1 += x * m[j].y;
            a2 += x * m[j].z; a3 += x * m[j].w;
        }
    }
}

// ---------------- step pass A ----------------
// w2 partials -> w2 AND wsum; (w1 + onehot) s-slice -> wsum.
// Entire stream independent of k_init; waits only before the atomics.
__global__ void __launch_bounds__(256) k_stepA(
    const float* __restrict__ step,
    const int* __restrict__ qidx, const float* __restrict__ qmask)
{
    pdl_trigger();
    __shared__ float xs[ROWS];
    const int b  = blockIdx.y;
    const int s0 = blockIdx.x * ROWS;
    const int t0 = threadIdx.x * 4;
    const int q = qidx[b];
    const float m = qmask[b];
    const float* stepb = step + (size_t)b * SS * SS;
    const float* Mb = stepb + (size_t)s0 * SS;

    float w1v = 0.f;
    if (threadIdx.x < ROWS) {
        w1v = m * __ldg(stepb + (size_t)q * SS + s0 + threadIdx.x);
        xs[threadIdx.x] = w1v;
    }
    __syncthreads();

    float4 m0[8];
#pragma unroll
    for (int j = 0; j < 8; ++j)
        m0[j] = __ldcs(reinterpret_cast<const float4*>(Mb + (size_t)j * SS + t0));

    float a0 = 0.f, a1 = 0.f, a2 = 0.f, a3 = 0.f;
    matvec_acc(Mb, m0, xs, t0, a0, a1, a2, a3);

    pdl_wait();   // k_init must have zeroed zbuf before any atomics land
    float* yw = g_zbuf + OFF_W2 + b * SS + t0;
    atomicAdd(yw + 0, a0); atomicAdd(yw + 1, a1);
    atomicAdd(yw + 2, a2); atomicAdd(yw + 3, a3);
    float* ys = g_zbuf + OFF_WSUM + b * SS + t0;
    atomicAdd(ys + 0, a0); atomicAdd(ys + 1, a1);
    atomicAdd(ys + 2, a2); atomicAdd(ys + 3, a3);
    if (threadIdx.x < ROWS) {
        int s = s0 + threadIdx.x;
        float v = w1v + ((s == q) ? m : 0.f);
        atomicAdd(g_zbuf + OFF_WSUM + b * SS + s, v);
    }
}

// ---------------- step pass B: wsum += w2_chunk @ step[b] (w3 part) ---------
__global__ void __launch_bounds__(256) k_stepB(const float* __restrict__ step)
{
    pdl_trigger();
    __shared__ float xs[ROWS];
    const int b  = blockIdx.y;
    const int s0 = blockIdx.x * ROWS;
    const int t0 = threadIdx.x * 4;
    const float* Mb = step + (size_t)b * SS * SS + (size_t)s0 * SS;

    float4 m0[8];
#pragma unroll
    for (int j = 0; j < 8; ++j)
        m0[j] = __ldcs(reinterpret_cast<const float4*>(Mb + (size_t)j * SS + t0));

    pdl_wait();
    if (threadIdx.x < ROWS)
        xs[threadIdx.x] = __ldcg(g_zbuf + OFF_W2 + b * SS + s0 + threadIdx.x);
    __syncthreads();

    float a0 = 0.f, a1 = 0.f, a2 = 0.f, a3 = 0.f;
    matvec_acc(Mb, m0, xs, t0, a0, a1, a2, a3);

    float* y = g_zbuf + OFF_WSUM + b * SS + t0;
    atomicAdd(y + 0, a0); atomicAdd(y + 1, a1);
    atomicAdd(y + 2, a2); atomicAdd(y + 3, a3);
}

// ---------------- map pass: accv += wsum_chunk @ map ----------------
__global__ void __launch_bounds__(256) k_mapC(const float* __restrict__ map)
{
    pdl_trigger();
    __shared__ float xs[ROWS];
    const int b  = blockIdx.y;
    const int s0 = blockIdx.x * ROWS;
    const int t0 = threadIdx.x * 4;
    const float* Mb = map + (size_t)b * SS * SS + (size_t)s0 * SS;

    float4 m0[8];
#pragma unroll
    for (int j = 0; j < 8; ++j)
        m0[j] = __ldcs(reinterpret_cast<const float4*>(Mb + (size_t)j * SS + t0));

    pdl_wait();   // wsum complete (transitively: stepB done before GEMM1a done)
    if (threadIdx.x < ROWS)
        xs[threadIdx.x] = __ldcg(g_zbuf + OFF_WSUM + b * SS + s0 + threadIdx.x);
    __syncthreads();

    float a0 = 0.f, a1 = 0.f, a2 = 0.f, a3 = 0.f;
    matvec_acc(Mb, m0, xs, t0, a0, a1, a2, a3);

    float* y = g_zbuf + OFF_ACCV + b * SS + t0;
    atomicAdd(y + 0, a0); atomicAdd(y + 1, a1);
    atomicAdd(y + 2, a2); atomicAdd(y + 3, a3);
}

// ---------------- gelu ----------------
__device__ __forceinline__ float gelu_tanh(float x) {
    float x3 = x * x * x;
    return 0.5f * x * (1.0f + tanhf(0.7978845608028654f * (x + 0.044715f * x3)));
}

// ---------------- split-K GEMM, f32x2 packed, double-buffered, PDL ----------
// C[64, 1024-per-z] += act(A[64,Ktot]) @ W[Ktot,1024]  (atomic accumulate)
// grid = (16 n-blocks, KSPLIT, Z), block = 256. BM=64 BN=64 BK=16, 4x4/thread.
template <int KSPLIT, int AGELU>
__global__ void __launch_bounds__(256) k_gemm(
    const float* __restrict__ A0, const float* __restrict__ A1,
    const float* __restrict__ bA0, const float* __restrict__ bA1,
    const float* __restrict__ W0, const float* __restrict__ W1,
    float* __restrict__ C0, float* __restrict__ C1,
    int lda, int ldc, int Ktot)
{
    pdl_trigger();
    const float* A  = blockIdx.z ? A1  : A0;
    const float* Ab = blockIdx.z ? bA1 : bA0;
    const float* W  = blockIdx.z ? W1  : W0;
    float*       C  = blockIdx.z ? C1  : C0;

    const int n0 = blockIdx.x * 64;
    const int kchunk = Ktot / KSPLIT;
    const int k0 = blockIdx.y * kchunk;
    const int T  = kchunk / 16;          // tiles per CTA

    __shared__ float As[2][16][68];
    __shared__ float Ws[2][16][64];

    const int tid = threadIdx.x;
    const int tx = tid & 15;
    const int ty = tid >> 4;

    ull acc2[4][2] = {};

    const int lm = tid >> 2;
    const int lk = (tid & 3) * 4;
    const int wk = tid >> 4;
    const int wn = (tid & 15) * 4;

    // prologue: W tile 0 is independent of upstream; A depends on it.
    {
        float4 w0 = *reinterpret_cast<const float4*>(W + (size_t)(k0 + wk) * 1024 + n0 + wn);
        pdl_wait();
        float4 a = *reinterpret_cast<const float4*>(A + (size_t)lm * lda + k0 + lk);
        if (AGELU) {
            const float* bp = Ab + k0 + lk;
            a.x = gelu_tanh(a.x + bp[0]);
            a.y = gelu_tanh(a.y + bp[1]);
            a.z = gelu_tanh(a.z + bp[2]);
            a.w = gelu_tanh(a.w + bp[3]);
        }
        As[0][lk + 0][lm] = a.x;
        As[0][lk + 1][lm] = a.y;
        As[0][lk + 2][lm] = a.z;
        As[0][lk + 3][lm] = a.w;
        *reinterpret_cast<float4*>(&Ws[0][wk][wn]) = w0;
    }
    __syncthreads();

#pragma unroll 1
    for (int t = 0; t < T; ++t) {
        const int cur = t & 1;
        const int nxt = cur ^ 1;

        float4 a_n, w_n;
        if (t + 1 < T) {
            const int kt = k0 + (t + 1) * 16;
            a_n = *reinterpret_cast<const float4*>(A + (size_t)lm * lda + kt + lk);
            w_n = *reinterpret_cast<const float4*>(W + (size_t)(kt + wk) * 1024 + n0 + wn);
        }

#pragma unroll
        for (int k = 0; k < 16; ++k) {
            float4 av = *reinterpret_cast<const float4*>(&As[cur][k][ty * 4]);
            const ull* bp = reinterpret_cast<const ull*>(&Ws[cur][k][tx * 4]);
            ull b01 = bp[0];
            ull b23 = bp[1];
            ull ax = pack_bcast(av.x);
            ull ay = pack_bcast(av.y);
            ull az = pack_bcast(av.z);
            ull aw = pack_bcast(av.w);
            acc2[0][0] = fma2(ax, b01, acc2[0][0]);
            acc2[0][1] = fma2(ax, b23, acc2[0][1]);
            acc2[1][0] = fma2(ay, b01, acc2[1][0]);
            acc2[1][1] = fma2(ay, b23, acc2[1][1]);
            acc2[2][0] = fma2(az, b01, acc2[2][0]);
            acc2[2][1] = fma2(az, b23, acc2[2][1]);
            acc2[3][0] = fma2(aw, b01, acc2[3][0]);
            acc2[3][1] = fma2(aw, b23, acc2[3][1]);
        }

        if (t + 1 < T) {
            const int kt = k0 + (t + 1) * 16;
            if (AGELU) {
                const float* bp = Ab + kt + lk;
                a_n.x = gelu_tanh(a_n.x + bp[0]);
                a_n.y = gelu_tanh(a_n.y + bp[1]);
                a_n.z = gelu_tanh(a_n.z + bp[2]);
                a_n.w = gelu_tanh(a_n.w + bp[3]);
            }
            As[nxt][lk + 0][lm] = a_n.x;
            As[nxt][lk + 1][lm] = a_n.y;
            As[nxt][lk + 2][lm] = a_n.z;
            As[nxt][lk + 3][lm] = a_n.w;
            *reinterpret_cast<float4*>(&Ws[nxt][wk][wn]) = w_n;
            __syncthreads();
        }
    }

#pragma unroll
    for (int i = 0; i < 4; ++i) {
        int m = ty * 4 + i;
        float2 p0 = unpack2(acc2[i][0]);
        float2 p1 = unpack2(acc2[i][1]);
        float* cp = &C[(size_t)m * ldc + n0 + tx * 4];
        atomicAdd(cp + 0, p0.x);
        atomicAdd(cp + 1, p0.y);
        atomicAdd(cp + 2, p1.x);
        atomicAdd(cp + 3, p1.y);
    }
}

// ---------------- init: zero zbuf + pre-bias d_out (one kernel) ----------------
__global__ void k_init(float* __restrict__ out,
                       const float* __restrict__ bo2,
                       const float* __restrict__ bf2) {
    pdl_trigger();
    int i = blockIdx.x * blockDim.x + threadIdx.x;
    if (i < NZ / 4) {
        *reinterpret_cast<float4*>(g_zbuf + i * 4) = make_float4(0.f, 0.f, 0.f, 0.f);
    } else {
        int e0 = (i - NZ / 4) * 4;                  // 0 .. 131071
        int n = e0 & 1023;
        const float* bp = (e0 < BB * VV) ? (bo2 + n) : (bf2 + n);
        *reinterpret_cast<float4*>(out + e0) = *reinterpret_cast<const float4*>(bp);
    }
}

// ---------------- launch helpers ----------------
template <typename K, typename... Args>
static void launch_pdl(K kern, dim3 grid, dim3 block, Args... args) {
    cudaLaunchConfig_t cfg = {};
    cfg.gridDim = grid;
    cfg.blockDim = block;
    cfg.dynamicSmemBytes = 0;
    cfg.stream = 0;
    cudaLaunchAttribute attr[1];
    attr[0].id = cudaLaunchAttributeProgrammaticStreamSerialization;
    attr[0].val.programmaticStreamSerializationAllowed = 1;
    cfg.attrs = attr;
    cfg.numAttrs = 1;
    cudaLaunchKernelEx(&cfg, kern, args...);
}

// ---------------- launch ----------------
extern "C" void kernel_launch(void* const* d_in, const int* in_sizes, int n_in,
                              void* d_out, int out_size) {
    const float* map_memory  = (const float*)d_in[0];
    const float* step_memory = (const float*)d_in[1];
    const int*   query_idx   = (const int*)  d_in[2];
    const float* query_mask  = (const float*)d_in[3];
    const float* symbol_bank = (const float*)d_in[4];
    const float* value_bank  = (const float*)d_in[5];
    const float* Wo1 = (const float*)d_in[6];
    const float* bo1 = (const float*)d_in[7];
    const float* Wo2 = (const float*)d_in[8];
    const float* bo2 = (const float*)d_in[9];
    const float* Wf1 = (const float*)d_in[10];
    const float* bf1 = (const float*)d_in[11];
    const float* Wf2 = (const float*)d_in[12];
    const float* bf2 = (const float*)d_in[13];
    float* out = (float*)d_out;

    float* zbuf;
    cudaGetSymbolAddress((void**)&zbuf, g_zbuf);

    float* pwsum = zbuf + OFF_WSUM;
    float* paccv = zbuf + OFF_ACCV;
    float* pgs   = zbuf + OFF_GS;
    float* phpre = zbuf + OFF_HPRE;

    // zero accumulation targets + pre-bias d_out
    k_init<<<512, 256>>>(out, bo2, bf2);

    // walk, PDL-chained; wsum assembled by atomics across stepA/stepB
    dim3 mg(SS / ROWS, BB);
    launch_pdl(k_stepA, mg, dim3(256), step_memory, query_idx, query_mask);
    launch_pdl(k_stepB, mg, dim3(256), step_memory);

    // GEMM1a: gs += wsum @ symbol_bank — overlaps mapC (compute vs DRAM)
    dim3 g1(16, 16, 1);
    launch_pdl(k_gemm<16, 0>, g1, dim3(256),
               (const float*)pwsum, (const float*)pwsum,
               (const float*)nullptr, (const float*)nullptr,
               symbol_bank, symbol_bank, pgs, pgs, (int)SS, (int)DD, (int)SS);

    // map pass: accv += wsum @ map
    launch_pdl(k_mapC, mg, dim3(256), map_memory);

    // GEMM1b: gs += accv @ value_bank
    launch_pdl(k_gemm<16, 0>, g1, dim3(256),
               (const float*)paccv, (const float*)paccv,
               (const float*)nullptr, (const float*)nullptr,
               value_bank, value_bank, pgs, pgs, (int)VV, (int)DD, (int)VV);

    // hpre = [gs@Wo1 | gs@Wf1]
    dim3 gg(16, 16, 2);
    launch_pdl(k_gemm<16, 0>, gg, dim3(256),
               (const float*)pgs, (const float*)pgs,
               (const float*)nullptr, (const float*)nullptr,
               Wo1, Wf1, phpre, phpre + 1024, (int)DD, (int)2048, (int)DD);
    // out += [gelu(hpre_o+bo1)@Wo2 | gelu(hpre_f+bf1)@Wf2]
    launch_pdl(k_gemm<16, 1>, gg, dim3(256),
               (const float*)phpre, (const float*)(phpre + 1024), bo1, bf1,
               Wo2, Wf2, out, out + BB * VV, (int)2048, (int)1024, (int)DD);
}

// round 16
// speedup vs baseline: 1.0992x; 1.0992x over previous
#include <cuda_runtime.h>

#define BB 64
#define SS 1024
#define DD 1024
#define VV 1024

typedef unsigned long long ull;

// ---------------- scratch (no allocation allowed) ----------------
// zeroed-every-call region (zeroed by k_init):
//   [0]      w2    (64K floats)
//   [64K]    w3    (64K)
//   [128K]   accv  (64K)
//   [192K]   gs    (64K)
//   [256K]   hpre  (128K) -> [64][2048] (ho_pre | hf_pre)
__device__ float g_zbuf[BB * SS * 4 + BB * 2048];
// non-zeroed scratch: wsum (64K)
__device__ float g_buf[BB * SS];

#define OFF_W2   0
#define OFF_W3   (BB * SS)
#define OFF_ACCV (BB * SS * 2)
#define OFF_GS   (BB * SS * 3)
#define OFF_HPRE (BB * SS * 4)
#define NZ       (BB * SS * 4 + BB * 2048)   // 393216 floats to zero

#define OFF_WSUM 0

#define ROWS 128           // s-rows per CTA per pass (grid = 8 x 64 = 512 CTAs)
#define PF   16            // prefetch depth (rows batched per load group)

// ---- PDL primitives (no-ops when kernel not launched with the attribute) ----
__device__ __forceinline__ void pdl_trigger() {
    asm volatile("griddepcontrol.launch_dependents;");
}
__device__ __forceinline__ void pdl_wait() {
    asm volatile("griddepcontrol.wait;" ::: "memory");
}

// ---- f32x2 packed helpers (FFMA2 exists on sm_103a only via PTX) ----
__device__ __forceinline__ ull pack_bcast(float x) {
    ull r;
    asm("mov.b64 %0, {%1, %1};" : "=l"(r) : "r"(__float_as_uint(x)));
    return r;
}
__device__ __forceinline__ ull fma2(ull a, ull b, ull c) {
    ull r;
    asm("fma.rn.f32x2 %0, %1, %2, %3;" : "=l"(r) : "l"(a), "l"(b), "l"(c));
    return r;
}
__device__ __forceinline__ float2 unpack2(ull v) {
    unsigned lo, hi;
    asm("mov.b64 {%0, %1}, %2;" : "=r"(lo), "=r"(hi) : "l"(v));
    return make_float2(__uint_as_float(lo), __uint_as_float(hi));
}

// ---- matvec tail: rows PF..ROWS with first PF rows prefetched in m0 --------
// Accumulates, then (optionally) waits for PDL upstream before atomics.
__device__ __forceinline__ void matvec_rest(
    const float* __restrict__ Mb, const float4* m0, const float* xs, int t0,
    float* __restrict__ y, bool wait_before_atomic)
{
    float a0 = 0.f, a1 = 0.f, a2 = 0.f, a3 = 0.f;
#pragma unroll
    for (int j = 0; j < PF; ++j) {
        float x = xs[j];
        a0 += x * m0[j].x; a1 += x * m0[j].y;
        a2 += x * m0[j].z; a3 += x * m0[j].w;
    }
#pragma unroll 1
    for (int s = PF; s < ROWS; s += PF) {
        float4 m[PF];
#pragma unroll
        for (int j = 0; j < PF; ++j)
            m[j] = __ldcs(reinterpret_cast<const float4*>(Mb + (size_t)(s + j) * SS + t0));
#pragma unroll
        for (int j = 0; j < PF; ++j) {
            float x = xs[s + j];
            a0 += x * m[j].x; a1 += x * m[j].y;
            a2 += x * m[j].z; a3 += x * m[j].w;
        }
    }
    if (wait_before_atomic) pdl_wait();
    atomicAdd(y + 0, a0); atomicAdd(y + 1, a1);
    atomicAdd(y + 2, a2); atomicAdd(y + 3, a3);
}

// ---------------- step pass A: w2[b,:] += w1_chunk @ step[b] ----------------
// Entire stream is independent of k_init; waits only before the atomicAdds.
__global__ void __launch_bounds__(256) k_stepA(
    const float* __restrict__ step,
    const int* __restrict__ qidx, const float* __restrict__ qmask)
{
    pdl_trigger();
    __shared__ float xs[ROWS];
    const int b  = blockIdx.y;
    const int s0 = blockIdx.x * ROWS;
    const int t0 = threadIdx.x * 4;
    const float* stepb = step + (size_t)b * SS * SS;
    const float* Mb = stepb + (size_t)s0 * SS;

    if (threadIdx.x < ROWS) {
        int q = qidx[b];
        xs[threadIdx.x] = qmask[b] * __ldg(stepb + (size_t)q * SS + s0 + threadIdx.x);
    }
    __syncthreads();

    float4 m0[PF];
#pragma unroll
    for (int j = 0; j < PF; ++j)
        m0[j] = __ldcs(reinterpret_cast<const float4*>(Mb + (size_t)j * SS + t0));

    matvec_rest(Mb, m0, xs, t0, g_zbuf + OFF_W2 + b * SS + t0, true);
}

// ---------------- step pass B: w3[b,:] += w2_chunk @ step[b] ----------------
// Prefetch PF independent matrix rows before waiting on stepA's w2.
__global__ void __launch_bounds__(256) k_stepB(const float* __restrict__ step)
{
    pdl_trigger();
    __shared__ float xs[ROWS];
    const int b  = blockIdx.y;
    const int s0 = blockIdx.x * ROWS;
    const int t0 = threadIdx.x * 4;
    const float* Mb = step + (size_t)b * SS * SS + (size_t)s0 * SS;

    float4 m0[PF];
#pragma unroll
    for (int j = 0; j < PF; ++j)
        m0[j] = __ldcs(reinterpret_cast<const float4*>(Mb + (size_t)j * SS + t0));

    pdl_wait();
    if (threadIdx.x < ROWS)
        xs[threadIdx.x] = __ldcg(g_zbuf + OFF_W2 + b * SS + s0 + threadIdx.x);
    __syncthreads();

    matvec_rest(Mb, m0, xs, t0, g_zbuf + OFF_W3 + b * SS + t0, false);
}

// ---------------- map pass: wsum on the fly; accv += wsum_chunk @ map -------
__global__ void __launch_bounds__(256) k_mapC(
    const float* __restrict__ map, const float* __restrict__ step,
    const int* __restrict__ qidx, const float* __restrict__ qmask)
{
    pdl_trigger();
    __shared__ float xs[ROWS];
    const int b  = blockIdx.y;
    const int s0 = blockIdx.x * ROWS;
    const int t0 = threadIdx.x * 4;
    const int q = qidx[b];
    const float m = qmask[b];
    const float* Mb = map + (size_t)b * SS * SS + (size_t)s0 * SS;

    // independent: q-row contribution + first PF map rows
    float qv = 0.f;
    if (threadIdx.x < ROWS)
        qv = m * __ldg(step + ((size_t)b * SS + (size_t)q) * SS + s0 + threadIdx.x);

    float4 m0[PF];
#pragma unroll
    for (int j = 0; j < PF; ++j)
        m0[j] = __ldcs(reinterpret_cast<const float4*>(Mb + (size_t)j * SS + t0));

    pdl_wait();
    if (threadIdx.x < ROWS) {
        int s = s0 + threadIdx.x;
        float v = qv + __ldcg(g_zbuf + OFF_W2 + b * SS + s)
                     + __ldcg(g_zbuf + OFF_W3 + b * SS + s);
        if (s == q) v += m;
        xs[threadIdx.x] = v;
        g_buf[OFF_WSUM + b * SS + s] = v;   // consumed by symbol_bank GEMM
    }
    __syncthreads();

    matvec_rest(Mb, m0, xs, t0, g_zbuf + OFF_ACCV + b * SS + t0, false);
}

// ---------------- gelu ----------------
__device__ __forceinline__ float gelu_tanh(float x) {
    float x3 = x * x * x;
    return 0.5f * x * (1.0f + tanhf(0.7978845608028654f * (x + 0.044715f * x3)));
}

// ---------------- split-K GEMM, f32x2 packed, double-buffered, PDL ----------
// C[64, 1024-per-z] += act(A[64,Ktot]) @ W[Ktot,1024]  (atomic accumulate)
// grid = (16 n-blocks, KSPLIT, 2), block = 256. BM=64 BN=64 BK=16, 4x4/thread.
template <int KSPLIT, int AGELU>
__global__ void __launch_bounds__(256) k_gemm(
    const float* __restrict__ A0, const float* __restrict__ A1,
    const float* __restrict__ bA0, const float* __restrict__ bA1,
    const float* __restrict__ W0, const float* __restrict__ W1,
    float* __restrict__ C0, float* __restrict__ C1,
    int lda, int ldc, int Ktot)
{
    pdl_trigger();
    const float* A  = blockIdx.z ? A1  : A0;
    const float* Ab = blockIdx.z ? bA1 : bA0;
    const float* W  = blockIdx.z ? W1  : W0;
    float*       C  = blockIdx.z ? C1  : C0;

    const int n0 = blockIdx.x * 64;
    const int kchunk = Ktot / KSPLIT;
    const int k0 = blockIdx.y * kchunk;
    const int T  = kchunk / 16;          // tiles per CTA

    __shared__ float As[2][16][68];
    __shared__ float Ws[2][16][64];

    const int tid = threadIdx.x;
    const int tx = tid & 15;
    const int ty = tid >> 4;

    ull acc2[4][2] = {};

    const int lm = tid >> 2;
    const int lk = (tid & 3) * 4;
    const int wk = tid >> 4;
    const int wn = (tid & 15) * 4;

    // prologue: W tile 0 is independent of upstream; A depends on it.
    {
        float4 w0 = *reinterpret_cast<const float4*>(W + (size_t)(k0 + wk) * 1024 + n0 + wn);
        pdl_wait();
        float4 a = *reinterpret_cast<const float4*>(A + (size_t)lm * lda + k0 + lk);
        if (AGELU) {
            const float* bp = Ab + k0 + lk;
            a.x = gelu_tanh(a.x + bp[0]);
            a.y = gelu_tanh(a.y + bp[1]);
            a.z = gelu_tanh(a.z + bp[2]);
            a.w = gelu_tanh(a.w + bp[3]);
        }
        As[0][lk + 0][lm] = a.x;
        As[0][lk + 1][lm] = a.y;
        As[0][lk + 2][lm] = a.z;
        As[0][lk + 3][lm] = a.w;
        *reinterpret_cast<float4*>(&Ws[0][wk][wn]) = w0;
    }
    __syncthreads();

#pragma unroll 1
    for (int t = 0; t < T; ++t) {
        const int cur = t & 1;
        const int nxt = cur ^ 1;

        float4 a_n, w_n;
        if (t + 1 < T) {
            const int kt = k0 + (t + 1) * 16;
            a_n = *reinterpret_cast<const float4*>(A + (size_t)lm * lda + kt + lk);
            w_n = *reinterpret_cast<const float4*>(W + (size_t)(kt + wk) * 1024 + n0 + wn);
        }

#pragma unroll
        for (int k = 0; k < 16; ++k) {
            float4 av = *reinterpret_cast<const float4*>(&As[cur][k][ty * 4]);
            const ull* bp = reinterpret_cast<const ull*>(&Ws[cur][k][tx * 4]);
            ull b01 = bp[0];
            ull b23 = bp[1];
            ull ax = pack_bcast(av.x);
            ull ay = pack_bcast(av.y);
            ull az = pack_bcast(av.z);
            ull aw = pack_bcast(av.w);
            acc2[0][0] = fma2(ax, b01, acc2[0][0]);
            acc2[0][1] = fma2(ax, b23, acc2[0][1]);
            acc2[1][0] = fma2(ay, b01, acc2[1][0]);
            acc2[1][1] = fma2(ay, b23, acc2[1][1]);
            acc2[2][0] = fma2(az, b01, acc2[2][0]);
            acc2[2][1] = fma2(az, b23, acc2[2][1]);
            acc2[3][0] = fma2(aw, b01, acc2[3][0]);
            acc2[3][1] = fma2(aw, b23, acc2[3][1]);
        }

        if (t + 1 < T) {
            const int kt = k0 + (t + 1) * 16;
            if (AGELU) {
                const float* bp = Ab + kt + lk;
                a_n.x = gelu_tanh(a_n.x + bp[0]);
                a_n.y = gelu_tanh(a_n.y + bp[1]);
                a_n.z = gelu_tanh(a_n.z + bp[2]);
                a_n.w = gelu_tanh(a_n.w + bp[3]);
            }
            As[nxt][lk + 0][lm] = a_n.x;
            As[nxt][lk + 1][lm] = a_n.y;
            As[nxt][lk + 2][lm] = a_n.z;
            As[nxt][lk + 3][lm] = a_n.w;
            *reinterpret_cast<float4*>(&Ws[nxt][wk][wn]) = w_n;
            __syncthreads();
        }
    }

#pragma unroll
    for (int i = 0; i < 4; ++i) {
        int m = ty * 4 + i;
        float2 p0 = unpack2(acc2[i][0]);
        float2 p1 = unpack2(acc2[i][1]);
        float* cp = &C[(size_t)m * ldc + n0 + tx * 4];
        atomicAdd(cp + 0, p0.x);
        atomicAdd(cp + 1, p0.y);
        atomicAdd(cp + 2, p1.x);
        atomicAdd(cp + 3, p1.y);
    }
}

// ---------------- init: zero zbuf + pre-bias d_out (one kernel) ----------------
__global__ void k_init(float* __restrict__ out,
                       const float* __restrict__ bo2,
                       const float* __restrict__ bf2) {
    pdl_trigger();
    int i = blockIdx.x * blockDim.x + threadIdx.x;
    if (i < NZ / 4) {
        *reinterpret_cast<float4*>(g_zbuf + i * 4) = make_float4(0.f, 0.f, 0.f, 0.f);
    } else {
        int e0 = (i - NZ / 4) * 4;                  // 0 .. 131071
        int n = e0 & 1023;
        const float* bp = (e0 < BB * VV) ? (bo2 + n) : (bf2 + n);
        *reinterpret_cast<float4*>(out + e0) = *reinterpret_cast<const float4*>(bp);
    }
}

// ---------------- launch helpers ----------------
template <typename K, typename... Args>
static void launch_pdl(K kern, dim3 grid, dim3 block, Args... args) {
    cudaLaunchConfig_t cfg = {};
    cfg.gridDim = grid;
    cfg.blockDim = block;
    cfg.dynamicSmemBytes = 0;
    cfg.stream = 0;
    cudaLaunchAttribute attr[1];
    attr[0].id = cudaLaunchAttributeProgrammaticStreamSerialization;
    attr[0].val.programmaticStreamSerializationAllowed = 1;
    cfg.attrs = attr;
    cfg.numAttrs = 1;
    cudaLaunchKernelEx(&cfg, kern, args...);
}

// ---------------- launch ----------------
extern "C" void kernel_launch(void* const* d_in, const int* in_sizes, int n_in,
                              void* d_out, int out_size) {
    const float* map_memory  = (const float*)d_in[0];
    const float* step_memory = (const float*)d_in[1];
    const int*   query_idx   = (const int*)  d_in[2];
    const float* query_mask  = (const float*)d_in[3];
    const float* symbol_bank = (const float*)d_in[4];
    const float* value_bank  = (const float*)d_in[5];
    const float* Wo1 = (const float*)d_in[6];
    const float* bo1 = (const float*)d_in[7];
    const float* Wo2 = (const float*)d_in[8];
    const float* bo2 = (const float*)d_in[9];
    const float* Wf1 = (const float*)d_in[10];
    const float* bf1 = (const float*)d_in[11];
    const float* Wf2 = (const float*)d_in[12];
    const float* bf2 = (const float*)d_in[13];
    float* out = (float*)d_out;

    float *zbuf, *buf;
    cudaGetSymbolAddress((void**)&zbuf, g_zbuf);
    cudaGetSymbolAddress((void**)&buf,  g_buf);

    float* pwsum = buf  + OFF_WSUM;
    float* paccv = zbuf + OFF_ACCV;
    float* pgs   = zbuf + OFF_GS;
    float* phpre = zbuf + OFF_HPRE;

    // zero accumulation targets + pre-bias d_out
    k_init<<<512, 256>>>(out, bo2, bf2);

    // walk: 512-CTA passes, PDL-chained (each overlaps predecessor's tail)
    dim3 mg(SS / ROWS, BB);
    launch_pdl(k_stepA, mg, dim3(256), step_memory, query_idx, query_mask);
    launch_pdl(k_stepB, mg, dim3(256), step_memory);
    launch_pdl(k_mapC,  mg, dim3(256), map_memory, step_memory, query_idx, query_mask);

    // gs = wsum@symbol_bank + accv@value_bank   (z-paired, both into pgs)
    dim3 gg(16, 16, 2);
    launch_pdl(k_gemm<16, 0>, gg, dim3(256),
               (const float*)pwsum, (const float*)paccv,
               (const float*)nullptr, (const float*)nullptr,
               symbol_bank, value_bank, pgs, pgs, (int)SS, (int)DD, (int)SS);
    // hpre = [gs@Wo1 | gs@Wf1]
    launch_pdl(k_gemm<16, 0>, gg, dim3(256),
               (const float*)pgs, (const float*)pgs,
               (const float*)nullptr, (const float*)nullptr,
               Wo1, Wf1, phpre, phpre + 1024, (int)DD, (int)2048, (int)DD);
    // out += [gelu(hpre_o+bo1)@Wo2 | gelu(hpre_f+bf1)@Wf2]
    launch_pdl(k_gemm<16, 1>, gg, dim3(256),
               (const float*)phpre, (const float*)(phpre + 1024), bo1, bf1,
               Wo2, Wf2, out, out + BB * VV, (int)2048, (int)1024, (int)DD);
}

// round 17
// speedup vs baseline: 1.1092x; 1.0091x over previous
#include <cuda_runtime.h>

#define BB 64
#define SS 1024
#define DD 1024
#define VV 1024

typedef unsigned long long ull;

// ---------------- scratch (no allocation allowed) ----------------
// zeroed-every-call region (zeroed by k_init):
//   [0]      w2    (64K floats)
//   [64K]    w3    (64K)
//   [128K]   accv  (64K)
//   [192K]   gs    (64K)
//   [256K]   hpre  (128K) -> [64][2048] (ho_pre | hf_pre)
__device__ float g_zbuf[BB * SS * 4 + BB * 2048];
// non-zeroed scratch: wsum (64K)
__device__ float g_buf[BB * SS];

#define OFF_W2   0
#define OFF_W3   (BB * SS)
#define OFF_ACCV (BB * SS * 2)
#define OFF_GS   (BB * SS * 3)
#define OFF_HPRE (BB * SS * 4)
#define NZ       (BB * SS * 4 + BB * 2048)   // 393216 floats to zero

#define OFF_WSUM 0

#define ROWS 128           // s-rows per CTA per pass (grid = 8 x 64 = 512 CTAs)
#define PF   16            // prefetch depth (rows batched per load group)

// ---- PDL primitives ----
__device__ __forceinline__ void pdl_trigger() {
    asm volatile("griddepcontrol.launch_dependents;");
}
__device__ __forceinline__ void pdl_wait() {
    asm volatile("griddepcontrol.wait;" ::: "memory");
}

// ---- f32x2 packed helpers (FFMA2 exists on sm_103a only via PTX) ----
__device__ __forceinline__ ull pack_bcast(float x) {
    ull r;
    asm("mov.b64 %0, {%1, %1};" : "=l"(r) : "r"(__float_as_uint(x)));
    return r;
}
__device__ __forceinline__ ull fma2(ull a, ull b, ull c) {
    ull r;
    asm("fma.rn.f32x2 %0, %1, %2, %3;" : "=l"(r) : "l"(a), "l"(b), "l"(c));
    return r;
}
__device__ __forceinline__ float2 unpack2(ull v) {
    unsigned lo, hi;
    asm("mov.b64 {%0, %1}, %2;" : "=r"(lo), "=r"(hi) : "l"(v));
    return make_float2(__uint_as_float(lo), __uint_as_float(hi));
}

// ---- matvec accumulate over ROWS rows, PF-deep batching ----
// STREAM=1: __ldcs (evict-first). STREAM=0: default (retain in L2 for reuse).
template <int STREAM>
__device__ __forceinline__ void matvec_acc(
    const float* __restrict__ Mb, const float* xs, int t0,
    float& a0, float& a1, float& a2, float& a3)
{
#pragma unroll 1
    for (int s = 0; s < ROWS; s += PF) {
        float4 m[PF];
#pragma unroll
        for (int j = 0; j < PF; ++j) {
            const float4* p = reinterpret_cast<const float4*>(Mb + (size_t)(s + j) * SS + t0);
            m[j] = STREAM ? __ldcs(p) : __ldg(p);
        }
#pragma unroll
        for (int j = 0; j < PF; ++j) {
            float x = xs[s + j];
            a0 += x * m[j].x; a1 += x * m[j].y;
            a2 += x * m[j].z; a3 += x * m[j].w;
        }
    }
}

// ---------------- fused step pass (cluster = 8 CTAs = one batch) ------------
// Phase 1: w2[b] partials from w1 (q-row) @ step[b], loads RETAINED in L2.
// cluster barrier (intra-batch dependency only), then
// Phase 2: w3[b] partials from w2[b] @ step[b] — same 4MB, partially L2-hot.
__global__ void __launch_bounds__(256) __cluster_dims__(8, 1, 1) k_step2(
    const float* __restrict__ step,
    const int* __restrict__ qidx, const float* __restrict__ qmask)
{
    pdl_trigger();
    __shared__ float xs[ROWS];
    const int b  = blockIdx.y;
    const int s0 = blockIdx.x * ROWS;
    const int t0 = threadIdx.x * 4;
    const float* stepb = step + (size_t)b * SS * SS;
    const float* Mb = stepb + (size_t)s0 * SS;

    // ---- phase 1 ----
    if (threadIdx.x < ROWS) {
        int q = qidx[b];
        xs[threadIdx.x] = qmask[b] * __ldg(stepb + (size_t)q * SS + s0 + threadIdx.x);
    }
    __syncthreads();

    float a0 = 0.f, a1 = 0.f, a2 = 0.f, a3 = 0.f;
    matvec_acc<0>(Mb, xs, t0, a0, a1, a2, a3);

    pdl_wait();   // k_init zeroed zbuf
    {
        float* y = g_zbuf + OFF_W2 + b * SS + t0;
        atomicAdd(y + 0, a0); atomicAdd(y + 1, a1);
        atomicAdd(y + 2, a2); atomicAdd(y + 3, a3);
    }
    __threadfence();   // make w2 atomics visible before cluster release
    asm volatile("barrier.cluster.arrive.aligned;" ::: "memory");
    asm volatile("barrier.cluster.wait.aligned;" ::: "memory");

    // ---- phase 2 ----
    __syncthreads();
    if (threadIdx.x < ROWS)
        xs[threadIdx.x] = __ldcg(g_zbuf + OFF_W2 + b * SS + s0 + threadIdx.x);
    __syncthreads();

    float c0 = 0.f, c1 = 0.f, c2 = 0.f, c3 = 0.f;
    matvec_acc<1>(Mb, xs, t0, c0, c1, c2, c3);

    float* y = g_zbuf + OFF_W3 + b * SS + t0;
    atomicAdd(y + 0, c0); atomicAdd(y + 1, c1);
    atomicAdd(y + 2, c2); atomicAdd(y + 3, c3);
}

// ---------------- map pass: wsum on the fly; accv += wsum_chunk @ map -------
__global__ void __launch_bounds__(256) k_mapC(
    const float* __restrict__ map, const float* __restrict__ step,
    const int* __restrict__ qidx, const float* __restrict__ qmask)
{
    pdl_trigger();
    __shared__ float xs[ROWS];
    const int b  = blockIdx.y;
    const int s0 = blockIdx.x * ROWS;
    const int t0 = threadIdx.x * 4;
    const int q = qidx[b];
    const float m = qmask[b];
    const float* Mb = map + (size_t)b * SS * SS + (size_t)s0 * SS;

    // independent prologue: q-row contribution + first PF map rows
    float qv = 0.f;
    if (threadIdx.x < ROWS)
        qv = m * __ldg(step + ((size_t)b * SS + (size_t)q) * SS + s0 + threadIdx.x);

    float4 m0[PF];
#pragma unroll
    for (int j = 0; j < PF; ++j)
        m0[j] = __ldcs(reinterpret_cast<const float4*>(Mb + (size_t)j * SS + t0));

    pdl_wait();
    if (threadIdx.x < ROWS) {
        int s = s0 + threadIdx.x;
        float v = qv + __ldcg(g_zbuf + OFF_W2 + b * SS + s)
                     + __ldcg(g_zbuf + OFF_W3 + b * SS + s);
        if (s == q) v += m;
        xs[threadIdx.x] = v;
        g_buf[OFF_WSUM + b * SS + s] = v;   // consumed by symbol_bank GEMM
    }
    __syncthreads();

    float a0 = 0.f, a1 = 0.f, a2 = 0.f, a3 = 0.f;
#pragma unroll
    for (int j = 0; j < PF; ++j) {
        float x = xs[j];
        a0 += x * m0[j].x; a1 += x * m0[j].y;
        a2 += x * m0[j].z; a3 += x * m0[j].w;
    }
#pragma unroll 1
    for (int s = PF; s < ROWS; s += PF) {
        float4 m2[PF];
#pragma unroll
        for (int j = 0; j < PF; ++j)
            m2[j] = __ldcs(reinterpret_cast<const float4*>(Mb + (size_t)(s + j) * SS + t0));
#pragma unroll
        for (int j = 0; j < PF; ++j) {
            float x = xs[s + j];
            a0 += x * m2[j].x; a1 += x * m2[j].y;
            a2 += x * m2[j].z; a3 += x * m2[j].w;
        }
    }

    float* y = g_zbuf + OFF_ACCV + b * SS + t0;
    atomicAdd(y + 0, a0); atomicAdd(y + 1, a1);
    atomicAdd(y + 2, a2); atomicAdd(y + 3, a3);
}

// ---------------- gelu ----------------
__device__ __forceinline__ float gelu_tanh(float x) {
    float x3 = x * x * x;
    return 0.5f * x * (1.0f + tanhf(0.7978845608028654f * (x + 0.044715f * x3)));
}

// ---------------- split-K GEMM, f32x2 packed, double-buffered, PDL ----------
// C[64, 1024-per-z] += act(A[64,Ktot]) @ W[Ktot,1024]  (atomic accumulate)
template <int KSPLIT, int AGELU>
__global__ void __launch_bounds__(256) k_gemm(
    const float* __restrict__ A0, const float* __restrict__ A1,
    const float* __restrict__ bA0, const float* __restrict__ bA1,
    const float* __restrict__ W0, const float* __restrict__ W1,
    float* __restrict__ C0, float* __restrict__ C1,
    int lda, int ldc, int Ktot)
{
    pdl_trigger();
    const float* A  = blockIdx.z ? A1  : A0;
    const float* Ab = blockIdx.z ? bA1 : bA0;
    const float* W  = blockIdx.z ? W1  : W0;
    float*       C  = blockIdx.z ? C1  : C0;

    const int n0 = blockIdx.x * 64;
    const int kchunk = Ktot / KSPLIT;
    const int k0 = blockIdx.y * kchunk;
    const int T  = kchunk / 16;          // tiles per CTA

    __shared__ float As[2][16][68];
    __shared__ float Ws[2][16][64];

    const int tid = threadIdx.x;
    const int tx = tid & 15;
    const int ty = tid >> 4;

    ull acc2[4][2] = {};

    const int lm = tid >> 2;
    const int lk = (tid & 3) * 4;
    const int wk = tid >> 4;
    const int wn = (tid & 15) * 4;

    // prologue: W tile 0 independent of upstream; A depends on it.
    {
        float4 w0 = *reinterpret_cast<const float4*>(W + (size_t)(k0 + wk) * 1024 + n0 + wn);
        pdl_wait();
        float4 a = *reinterpret_cast<const float4*>(A + (size_t)lm * lda + k0 + lk);
        if (AGELU) {
            const float* bp = Ab + k0 + lk;
            a.x = gelu_tanh(a.x + bp[0]);
            a.y = gelu_tanh(a.y + bp[1]);
            a.z = gelu_tanh(a.z + bp[2]);
            a.w = gelu_tanh(a.w + bp[3]);
        }
        As[0][lk + 0][lm] = a.x;
        As[0][lk + 1][lm] = a.y;
        As[0][lk + 2][lm] = a.z;
        As[0][lk + 3][lm] = a.w;
        *reinterpret_cast<float4*>(&Ws[0][wk][wn]) = w0;
    }
    __syncthreads();

#pragma unroll 1
    for (int t = 0; t < T; ++t) {
        const int cur = t & 1;
        const int nxt = cur ^ 1;

        float4 a_n, w_n;
        if (t + 1 < T) {
            const int kt = k0 + (t + 1) * 16;
            a_n = *reinterpret_cast<const float4*>(A + (size_t)lm * lda + kt + lk);
            w_n = *reinterpret_cast<const float4*>(W + (size_t)(kt + wk) * 1024 + n0 + wn);
        }

#pragma unroll
        for (int k = 0; k < 16; ++k) {
            float4 av = *reinterpret_cast<const float4*>(&As[cur][k][ty * 4]);
            const ull* bp = reinterpret_cast<const ull*>(&Ws[cur][k][tx * 4]);
            ull b01 = bp[0];
            ull b23 = bp[1];
            ull ax = pack_bcast(av.x);
            ull ay = pack_bcast(av.y);
            ull az = pack_bcast(av.z);
            ull aw = pack_bcast(av.w);
            acc2[0][0] = fma2(ax, b01, acc2[0][0]);
            acc2[0][1] = fma2(ax, b23, acc2[0][1]);
            acc2[1][0] = fma2(ay, b01, acc2[1][0]);
            acc2[1][1] = fma2(ay, b23, acc2[1][1]);
            acc2[2][0] = fma2(az, b01, acc2[2][0]);
            acc2[2][1] = fma2(az, b23, acc2[2][1]);
            acc2[3][0] = fma2(aw, b01, acc2[3][0]);
            acc2[3][1] = fma2(aw, b23, acc2[3][1]);
        }

        if (t + 1 < T) {
            const int kt = k0 + (t + 1) * 16;
            if (AGELU) {
                const float* bp = Ab + kt + lk;
                a_n.x = gelu_tanh(a_n.x + bp[0]);
                a_n.y = gelu_tanh(a_n.y + bp[1]);
                a_n.z = gelu_tanh(a_n.z + bp[2]);
                a_n.w = gelu_tanh(a_n.w + bp[3]);
            }
            As[nxt][lk + 0][lm] = a_n.x;
            As[nxt][lk + 1][lm] = a_n.y;
            As[nxt][lk + 2][lm] = a_n.z;
            As[nxt][lk + 3][lm] = a_n.w;
            *reinterpret_cast<float4*>(&Ws[nxt][wk][wn]) = w_n;
            __syncthreads();
        }
    }

#pragma unroll
    for (int i = 0; i < 4; ++i) {
        int m = ty * 4 + i;
        float2 p0 = unpack2(acc2[i][0]);
        float2 p1 = unpack2(acc2[i][1]);
        float* cp = &C[(size_t)m * ldc + n0 + tx * 4];
        atomicAdd(cp + 0, p0.x);
        atomicAdd(cp + 1, p0.y);
        atomicAdd(cp + 2, p1.x);
        atomicAdd(cp + 3, p1.y);
    }
}

// ---------------- init: zero zbuf + pre-bias d_out (one kernel) ----------------
__global__ void k_init(float* __restrict__ out,
                       const float* __restrict__ bo2,
                       const float* __restrict__ bf2) {
    pdl_trigger();
    int i = blockIdx.x * blockDim.x + threadIdx.x;
    if (i < NZ / 4) {
        *reinterpret_cast<float4*>(g_zbuf + i * 4) = make_float4(0.f, 0.f, 0.f, 0.f);
    } else {
        int e0 = (i - NZ / 4) * 4;                  // 0 .. 131071
        int n = e0 & 1023;
        const float* bp = (e0 < BB * VV) ? (bo2 + n) : (bf2 + n);
        *reinterpret_cast<float4*>(out + e0) = *reinterpret_cast<const float4*>(bp);
    }
}

// ---------------- launch helpers ----------------
template <typename K, typename... Args>
static void launch_pdl(K kern, dim3 grid, dim3 block, Args... args) {
    cudaLaunchConfig_t cfg = {};
    cfg.gridDim = grid;
    cfg.blockDim = block;
    cfg.dynamicSmemBytes = 0;
    cfg.stream = 0;
    cudaLaunchAttribute attr[1];
    attr[0].id = cudaLaunchAttributeProgrammaticStreamSerialization;
    attr[0].val.programmaticStreamSerializationAllowed = 1;
    cfg.attrs = attr;
    cfg.numAttrs = 1;
    cudaLaunchKernelEx(&cfg, kern, args...);
}

// ---------------- launch ----------------
extern "C" void kernel_launch(void* const* d_in, const int* in_sizes, int n_in,
                              void* d_out, int out_size) {
    const float* map_memory  = (const float*)d_in[0];
    const float* step_memory = (const float*)d_in[1];
    const int*   query_idx   = (const int*)  d_in[2];
    const float* query_mask  = (const float*)d_in[3];
    const float* symbol_bank = (const float*)d_in[4];
    const float* value_bank  = (const float*)d_in[5];
    const float* Wo1 = (const float*)d_in[6];
    const float* bo1 = (const float*)d_in[7];
    const float* Wo2 = (const float*)d_in[8];
    const float* bo2 = (const float*)d_in[9];
    const float* Wf1 = (const float*)d_in[10];
    const float* bf1 = (const float*)d_in[11];
    const float* Wf2 = (const float*)d_in[12];
    const float* bf2 = (const float*)d_in[13];
    float* out = (float*)d_out;

    float *zbuf, *buf;
    cudaGetSymbolAddress((void**)&zbuf, g_zbuf);
    cudaGetSymbolAddress((void**)&buf,  g_buf);

    float* pwsum = buf  + OFF_WSUM;
    float* paccv = zbuf + OFF_ACCV;
    float* pgs   = zbuf + OFF_GS;
    float* phpre = zbuf + OFF_HPRE;

    // zero accumulation targets + pre-bias d_out
    k_init<<<512, 256>>>(out, bo2, bf2);

    // fused step walk: one kernel, 8-CTA clusters own one batch each
    dim3 mg(SS / ROWS, BB);
    launch_pdl(k_step2, mg, dim3(256), step_memory, query_idx, query_mask);
    // map pass
    launch_pdl(k_mapC,  mg, dim3(256), map_memory, step_memory, query_idx, query_mask);

    // gs = wsum@symbol_bank + accv@value_bank   (z-paired, both into pgs)
    dim3 gg(16, 16, 2);
    launch_pdl(k_gemm<16, 0>, gg, dim3(256),
               (const float*)pwsum, (const float*)paccv,
               (const float*)nullptr, (const float*)nullptr,
               symbol_bank, value_bank, pgs, pgs, (int)SS, (int)DD, (int)SS);
    // hpre = [gs@Wo1 | gs@Wf1]
    launch_pdl(k_gemm<16, 0>, gg, dim3(256),
               (const float*)pgs, (const float*)pgs,
               (const float*)nullptr, (const float*)nullptr,
               Wo1, Wf1, phpre, phpre + 1024, (int)DD, (int)2048, (int)DD);
    // out += [gelu(hpre_o+bo1)@Wo2 | gelu(hpre_f+bf1)@Wf2]
    launch_pdl(k_gemm<16, 1>, gg, dim3(256),
               (const float*)phpre, (const float*)(phpre + 1024), bo1, bf1,
               Wo2, Wf2, out, out + BB * VV, (int)2048, (int)1024, (int)DD);
}